// round 5
// baseline (speedup 1.0000x reference)
#include <cuda_runtime.h>
#include <math.h>

#define NB 2
#define NC 21
#define NP 4096
#define TAPS 71
#define RAD 35
#define PTILE 512
#define QRANGE 128
#define QCH 8
#define NCHUNK 16
#define QSPL 32

__device__ float g_K[NB][NP][NP];
__device__ float g_feat[NB][NP][8];
__device__ float g_U[NB][NC][NP];
__device__ float g_q[NB][NC][NP];
__device__ float g_tmp[NB][NC][NP];
__device__ float g_comb[NB][NC][NP];
__device__ float g_qbf[NB][QSPL][NC][NP];
__device__ float g_g1[TAPS];

__device__ __forceinline__ float fexp2(float t) {
    t = fmaxf(t, -120.0f);
    float z  = t + 12582912.0f;
    int   ei = __float_as_int(z) - 0x4B400000;
    float f  = t - (z - 12582912.0f);
    float p  = fmaf(f, 0.001333355814642f, 0.009618129107629f);
    p = fmaf(f, p, 0.055504108664822f);
    p = fmaf(f, p, 0.240226506959101f);
    p = fmaf(f, p, 0.693147180559945f);
    p = fmaf(f, p, 1.0f);
    return __int_as_float(__float_as_int(p) + (ei << 23));
}

__global__ void prep_kernel(const float* __restrict__ unary,
                            const float* __restrict__ ref,
                            const float* __restrict__ kstd) {
    int t = blockIdx.x * 256 + threadIdx.x;
    if (t >= NB * NP) return;
    int n = t >> 12, p = t & (NP - 1);
    int y = p >> 6, x = p & 63;
    const float SQ = 1.2011224087864498f; // sqrt(log2 e)
    float f[5];
    f[0] = (float)y * (SQ / kstd[0]);
    f[1] = (float)x * (SQ / kstd[1]);
    f[2] = ref[(n * 3 + 0) * NP + p] * (SQ / kstd[2]);
    f[3] = ref[(n * 3 + 1) * NP + p] * (SQ / kstd[3]);
    f[4] = ref[(n * 3 + 2) * NP + p] * (SQ / kstd[4]);
    float a = 0.f;
#pragma unroll
    for (int k = 0; k < 5; k++) { g_feat[n][p][k] = f[k]; a = fmaf(f[k], f[k], a); }
    g_feat[n][p][5] = 0.5f * a;
    g_feat[n][p][6] = 0.f; g_feat[n][p][7] = 0.f;

    float pc[NC]; float s = 0.f;
#pragma unroll
    for (int c = 0; c < NC; c++) {
        float u = unary[(n * NC + c) * NP + p];
        u = fminf(fmaxf(u, 1e-5f), 1.0f);
        pc[c] = u; s += u;
        g_U[n][c][p] = logf(u);
    }
    float inv = 1.0f / s;
#pragma unroll
    for (int c = 0; c < NC; c++) g_q[n][c][p] = pc[c] * inv;
}

// gk = outer(r, r) with r = row sums (exact separable factor)
__global__ void g1_kernel(const float* __restrict__ gk) {
    int t = threadIdx.x;
    if (t < TAPS) {
        float s = 0.f;
        for (int j = 0; j < TAPS; j++) s += gk[t * TAPS + j];
        g_g1[t] = s;
    }
}

__global__ __launch_bounds__(256) void buildk_kernel() {
    __shared__ float fp[64][8];
    __shared__ float fq[64][8];
    int n = blockIdx.z;
    int P0 = blockIdx.y * 64, Q0 = blockIdx.x * 64;
    for (int i = threadIdx.x; i < 64 * 8; i += 256) {
        int r = i >> 3, k = i & 7;
        fp[r][k] = g_feat[n][P0 + r][k];
        fq[r][k] = g_feat[n][Q0 + r][k];
    }
    __syncthreads();
    int ql = threadIdx.x & 63;
    int pg = threadIdx.x >> 6;
    float q0 = fq[ql][0], q1 = fq[ql][1], q2 = fq[ql][2];
    float q3 = fq[ql][3], q4 = fq[ql][4], qa = fq[ql][5];
#pragma unroll
    for (int k = 0; k < 16; k++) {
        int pl = pg * 16 + k;
        float4 a4 = *(const float4*)&fp[pl][0];
        float2 a2 = *(const float2*)&fp[pl][4];
        float acc = -(a2.y + qa);
        acc = fmaf(a4.x, q0, acc);
        acc = fmaf(a4.y, q1, acc);
        acc = fmaf(a4.z, q2, acc);
        acc = fmaf(a4.w, q3, acc);
        acc = fmaf(a2.x, q4, acc);
        g_K[n][P0 + pl][Q0 + ql] = fexp2(acc); // = exp(-0.5*max(d2,0))
    }
}

// qbf_part[n][slot][c][p] = sum over 128-q range of K[p][q]*q[c][q]
// K staged via cp.async (coalesced, double-buffered, XOR-swizzled smem),
// inner product in packed fp32x2 (q-pairs), accumulators as f32x2.
__global__ __launch_bounds__(256, 2) void gemm_kernel() {
    __shared__ float kt[2][PTILE * QCH];   // 32KB
    __shared__ float qs[2][NC * QCH];      // 1.3KB
    int n = blockIdx.z;
    int pb = blockIdx.x * PTILE;
    int qb = blockIdx.y * QRANGE;
    int t = threadIdx.x;
    int w = t >> 5, l = t & 31;

    unsigned long long acc[2][NC];
#pragma unroll
    for (int j = 0; j < 2; j++)
#pragma unroll
        for (int c = 0; c < NC; c++) acc[j][c] = 0ULL;

#define PREFETCH(CH) do {                                                     \
        int buf_ = (CH) & 1;                                                  \
        int qoff_ = qb + (CH) * QCH;                                          \
        _Pragma("unroll")                                                     \
        for (int i_ = 0; i_ < 4; i_++) {                                      \
            int seg_ = i_ * 256 + t;                                          \
            int row_ = seg_ >> 1;                                             \
            int cg_  = seg_ & 1;                                              \
            int scg_ = cg_ ^ ((row_ >> 2) & 1);                               \
            const float* gp_ = &g_K[n][pb + row_][qoff_ + cg_ * 4];           \
            unsigned sa_ = (unsigned)__cvta_generic_to_shared(                \
                &kt[buf_][row_ * QCH + scg_ * 4]);                            \
            asm volatile("cp.async.cg.shared.global [%0], [%1], 16;"          \
                         :: "r"(sa_), "l"(gp_));                              \
        }                                                                     \
        if (t < 2 * NC) {                                                     \
            int c_ = t >> 1, cg_ = t & 1;                                     \
            const float* gp_ = &g_q[n][c_][qoff_ + cg_ * 4];                  \
            unsigned sa_ = (unsigned)__cvta_generic_to_shared(                \
                &qs[buf_][c_ * QCH + cg_ * 4]);                               \
            asm volatile("cp.async.cg.shared.global [%0], [%1], 16;"          \
                         :: "r"(sa_), "l"(gp_));                              \
        }                                                                     \
        asm volatile("cp.async.commit_group;");                               \
    } while (0)

    PREFETCH(0);
    int r0 = w * 64 + l;
    int sw = (r0 >> 2) & 1;

#pragma unroll 1
    for (int ch = 0; ch < NCHUNK; ch++) {
        int buf = ch & 1;
        if (ch + 1 < NCHUNK) {
            PREFETCH(ch + 1);
            asm volatile("cp.async.wait_group 1;");
        } else {
            asm volatile("cp.async.wait_group 0;");
        }
        __syncthreads();
#pragma unroll
        for (int g = 0; g < 2; g++) {
            int pg = (g ^ sw) * 4;
            ulonglong2 k0 = *(const ulonglong2*)&kt[buf][r0 * QCH + pg];
            ulonglong2 k1 = *(const ulonglong2*)&kt[buf][(r0 + 32) * QCH + pg];
#pragma unroll
            for (int c = 0; c < NC; c++) {
                ulonglong2 qv = *(const ulonglong2*)&qs[buf][c * QCH + g * 4];
                asm("fma.rn.f32x2 %0, %1, %2, %0;" : "+l"(acc[0][c]) : "l"(k0.x), "l"(qv.x));
                asm("fma.rn.f32x2 %0, %1, %2, %0;" : "+l"(acc[0][c]) : "l"(k0.y), "l"(qv.y));
                asm("fma.rn.f32x2 %0, %1, %2, %0;" : "+l"(acc[1][c]) : "l"(k1.x), "l"(qv.x));
                asm("fma.rn.f32x2 %0, %1, %2, %0;" : "+l"(acc[1][c]) : "l"(k1.y), "l"(qv.y));
            }
        }
        __syncthreads();
    }
#undef PREFETCH

#pragma unroll
    for (int j = 0; j < 2; j++) {
        int p = pb + r0 + j * 32;
#pragma unroll
        for (int c = 0; c < NC; c++) {
            unsigned long long a = acc[j][c];
            float lo = __uint_as_float((unsigned)a);
            float hi = __uint_as_float((unsigned)(a >> 32));
            g_qbf[n][blockIdx.y][c][p] = lo + hi;
        }
    }
}

__global__ void convy_kernel() {
    int t = blockIdx.x * 256 + threadIdx.x; // < NC*NP
    int n = blockIdx.y;
    int c = t >> 12, p = t & 4095;
    int y = p >> 6, x = p & 63;
    int j0 = max(0, y - RAD), j1 = min(63, y + RAD);
    const float* col = &g_q[n][c][x];
    float s = 0.f;
    for (int j = j0; j <= j1; j++) s = fmaf(g_g1[j - y + RAD], col[j * 64], s);
    g_tmp[n][c][p] = s;
}

__global__ void combine_kernel() {
    int t = blockIdx.x * 256 + threadIdx.x; // < NC*NP
    int n = blockIdx.y;
    int c = t >> 12, p = t & 4095;
    int y = p >> 6, x = p & 63;
    int j0 = max(0, x - RAD), j1 = min(63, x + RAD);
    const float* row = &g_tmp[n][c][y * 64];
    float s = 0.f;
    for (int j = j0; j <= j1; j++) s = fmaf(g_g1[j - x + RAD], row[j], s);
    float b = 0.f;
#pragma unroll 8
    for (int sl = 0; sl < QSPL; sl++) b += g_qbf[n][sl][c][p];
    g_comb[n][c][p] = fmaf(4.0f, b, 2.0f * s); // COMPAT_BF, COMPAT_SPATIAL
}

__global__ void fuse_kernel(float* __restrict__ dout, int last) {
    int t = blockIdx.x * 256 + threadIdx.x;
    if (t >= NB * NP) return;
    int n = t >> 12, p = t & 4095;
    float logit[NC]; float m = -1e30f;
#pragma unroll
    for (int c = 0; c < NC; c++) {
        float lg = g_U[n][c][p] + g_comb[n][c][p];
        logit[c] = lg; m = fmaxf(m, lg);
    }
    float sum = 0.f;
#pragma unroll
    for (int c = 0; c < NC; c++) { float e = __expf(logit[c] - m); logit[c] = e; sum += e; }
    float inv = 1.0f / sum;
#pragma unroll
    for (int c = 0; c < NC; c++) {
        float qq = logit[c] * inv;
        g_q[n][c][p] = qq;
        if (last) dout[(n * NC + c) * NP + p] = qq;
    }
}

extern "C" void kernel_launch(void* const* d_in, const int* in_sizes, int n_in,
                              void* d_out, int out_size) {
    const float* unary = (const float*)d_in[0];
    const float* ref   = (const float*)d_in[1];
    const float* gk    = (const float*)d_in[2];
    const float* kstd  = (const float*)d_in[3];
    float* dout = (float*)d_out;

    prep_kernel<<<32, 256>>>(unary, ref, kstd);
    g1_kernel<<<1, 128>>>(gk);
    buildk_kernel<<<dim3(64, 64, NB), 256>>>();
    for (int it = 0; it < 5; it++) {
        gemm_kernel<<<dim3(NP / PTILE, QSPL, NB), 256>>>();
        convy_kernel<<<dim3(336, NB), 256>>>();
        combine_kernel<<<dim3(336, NB), 256>>>();
        fuse_kernel<<<32, 256>>>(dout, it == 4);
    }
}

// round 6
// speedup vs baseline: 1.3969x; 1.3969x over previous
#include <cuda_runtime.h>
#include <math.h>

#define NB 2
#define NC 21
#define NP 4096
#define TAPS 71
#define RAD 35
#define PT 64
#define QBLK 1024
#define QCH 32
#define NCHUNK (QBLK / QCH)
#define QSPL (NP / QBLK)

__device__ float g_K[NB][NP][NP];
__device__ float g_feat[NB][NP][8];
__device__ float g_U[NB][NC][NP];
__device__ float g_q[NB][NC][NP];
__device__ float g_tmp[NB][NC][NP];
__device__ float g_comb[NB][NC][NP];
__device__ float g_qbf[NB][QSPL][NC][NP];
__device__ float g_g1[TAPS];

__device__ __forceinline__ float fexp2(float t) {
    t = fmaxf(t, -120.0f);
    float z  = t + 12582912.0f;
    int   ei = __float_as_int(z) - 0x4B400000;
    float f  = t - (z - 12582912.0f);
    float p  = fmaf(f, 0.001333355814642f, 0.009618129107629f);
    p = fmaf(f, p, 0.055504108664822f);
    p = fmaf(f, p, 0.240226506959101f);
    p = fmaf(f, p, 0.693147180559945f);
    p = fmaf(f, p, 1.0f);
    return __int_as_float(__float_as_int(p) + (ei << 23));
}

__global__ void prep_kernel(const float* __restrict__ unary,
                            const float* __restrict__ ref,
                            const float* __restrict__ kstd) {
    int t = blockIdx.x * 256 + threadIdx.x;
    if (t >= NB * NP) return;
    int n = t >> 12, p = t & (NP - 1);
    int y = p >> 6, x = p & 63;
    const float SQ = 1.2011224087864498f; // sqrt(log2 e)
    float f[5];
    f[0] = (float)y * (SQ / kstd[0]);
    f[1] = (float)x * (SQ / kstd[1]);
    f[2] = ref[(n * 3 + 0) * NP + p] * (SQ / kstd[2]);
    f[3] = ref[(n * 3 + 1) * NP + p] * (SQ / kstd[3]);
    f[4] = ref[(n * 3 + 2) * NP + p] * (SQ / kstd[4]);
    float a = 0.f;
#pragma unroll
    for (int k = 0; k < 5; k++) { g_feat[n][p][k] = f[k]; a = fmaf(f[k], f[k], a); }
    g_feat[n][p][5] = 0.5f * a;
    g_feat[n][p][6] = 0.f; g_feat[n][p][7] = 0.f;

    float pc[NC]; float s = 0.f;
#pragma unroll
    for (int c = 0; c < NC; c++) {
        float u = unary[(n * NC + c) * NP + p];
        u = fminf(fmaxf(u, 1e-5f), 1.0f);
        pc[c] = u; s += u;
        g_U[n][c][p] = logf(u);
    }
    float inv = 1.0f / s;
#pragma unroll
    for (int c = 0; c < NC; c++) g_q[n][c][p] = pc[c] * inv;
}

// gk = outer(r, r) with r = row sums (exact separable factor)
__global__ void g1_kernel(const float* __restrict__ gk) {
    int t = threadIdx.x;
    if (t < TAPS) {
        float s = 0.f;
        for (int j = 0; j < TAPS; j++) s += gk[t * TAPS + j];
        g_g1[t] = s;
    }
}

__global__ __launch_bounds__(256) void buildk_kernel() {
    __shared__ float fp[64][8];
    __shared__ float fq[64][8];
    int n = blockIdx.z;
    int P0 = blockIdx.y * 64, Q0 = blockIdx.x * 64;
    for (int i = threadIdx.x; i < 64 * 8; i += 256) {
        int r = i >> 3, k = i & 7;
        fp[r][k] = g_feat[n][P0 + r][k];
        fq[r][k] = g_feat[n][Q0 + r][k];
    }
    __syncthreads();
    int ql = threadIdx.x & 63;
    int pg = threadIdx.x >> 6;
    float q0 = fq[ql][0], q1 = fq[ql][1], q2 = fq[ql][2];
    float q3 = fq[ql][3], q4 = fq[ql][4], qa = fq[ql][5];
#pragma unroll
    for (int k = 0; k < 16; k++) {
        int pl = pg * 16 + k;
        float4 a4 = *(const float4*)&fp[pl][0];
        float2 a2 = *(const float2*)&fp[pl][4];
        float acc = -(a2.y + qa);
        acc = fmaf(a4.x, q0, acc);
        acc = fmaf(a4.y, q1, acc);
        acc = fmaf(a4.z, q2, acc);
        acc = fmaf(a4.w, q3, acc);
        acc = fmaf(a2.x, q4, acc);
        g_K[n][P0 + pl][Q0 + ql] = fexp2(acc); // = exp(-0.5*max(d2,0))
    }
}

// Block: 64 p-rows x 1024 q. Chunk: 32 q -> 64 rows x 128B CONTIGUOUS per row.
// 3-stage cp.async pipeline; warps split q (warp w owns q-group w of 8);
// lane owns rows {l, l+32}; packed fp32x2 FMA; smem cross-warp q-reduction.
__global__ __launch_bounds__(256, 2) void gemm_kernel() {
    __shared__ union {
        struct { float kt[3][PT * QCH]; float qs[3][NC * QCH]; } p;
        float red[PT * NC * 8]; // 43KB
    } sm;
    int n = blockIdx.z;
    int pb = blockIdx.x * PT;
    int qb = blockIdx.y * QBLK;
    int t = threadIdx.x;
    int w = t >> 5, l = t & 31;

    unsigned long long acc[2][NC];
#pragma unroll
    for (int j = 0; j < 2; j++)
#pragma unroll
        for (int c = 0; c < NC; c++) acc[j][c] = 0ULL;

#define PREFETCH(CH) do {                                                     \
        if ((CH) < NCHUNK) {                                                  \
            int buf_ = (CH) % 3;                                              \
            int qoff_ = qb + (CH) * QCH;                                      \
            _Pragma("unroll")                                                 \
            for (int i_ = 0; i_ < 2; i_++) {                                  \
                int seg_ = i_ * 256 + t;                                      \
                int row_ = seg_ >> 3;                                         \
                int gi_  = seg_ & 7;                                          \
                const float* gp_ = &g_K[n][pb + row_][qoff_ + gi_ * 4];       \
                unsigned sa_ = (unsigned)__cvta_generic_to_shared(            \
                    &sm.p.kt[buf_][row_ * QCH + ((gi_ ^ (row_ & 7)) << 2)]);  \
                asm volatile("cp.async.cg.shared.global [%0], [%1], 16;"      \
                             :: "r"(sa_), "l"(gp_));                          \
            }                                                                 \
            if (t < NC * 8) {                                                 \
                int c_ = t >> 3, gi_ = t & 7;                                 \
                const float* gp_ = &g_q[n][c_][qoff_ + gi_ * 4];              \
                unsigned sa_ = (unsigned)__cvta_generic_to_shared(            \
                    &sm.p.qs[buf_][c_ * QCH + gi_ * 4]);                      \
                asm volatile("cp.async.cg.shared.global [%0], [%1], 16;"      \
                             :: "r"(sa_), "l"(gp_));                          \
            }                                                                 \
        }                                                                     \
        asm volatile("cp.async.commit_group;");                               \
    } while (0)

    PREFETCH(0);
    PREFETCH(1);
    int g0 = (w ^ (l & 7)) << 2;

#pragma unroll 1
    for (int ch = 0; ch < NCHUNK; ch++) {
        PREFETCH(ch + 2);
        asm volatile("cp.async.wait_group 2;");
        __syncthreads();
        int buf = ch % 3;
        const float* kb = sm.p.kt[buf];
        const float* qp = sm.p.qs[buf];
        ulonglong2 k0 = *(const ulonglong2*)&kb[l * QCH + g0];
        ulonglong2 k1 = *(const ulonglong2*)&kb[(l + 32) * QCH + g0];
#pragma unroll
        for (int c = 0; c < NC; c++) {
            ulonglong2 qv = *(const ulonglong2*)&qp[c * QCH + (w << 2)];
            asm("fma.rn.f32x2 %0, %1, %2, %0;" : "+l"(acc[0][c]) : "l"(k0.x), "l"(qv.x));
            asm("fma.rn.f32x2 %0, %1, %2, %0;" : "+l"(acc[0][c]) : "l"(k0.y), "l"(qv.y));
            asm("fma.rn.f32x2 %0, %1, %2, %0;" : "+l"(acc[1][c]) : "l"(k1.x), "l"(qv.x));
            asm("fma.rn.f32x2 %0, %1, %2, %0;" : "+l"(acc[1][c]) : "l"(k1.y), "l"(qv.y));
        }
        __syncthreads();
    }
#undef PREFETCH

    // cross-warp q-reduction (warps hold disjoint q-subsets)
#pragma unroll
    for (int j = 0; j < 2; j++)
#pragma unroll
        for (int c = 0; c < NC; c++) {
            unsigned long long a = acc[j][c];
            float lo = __uint_as_float((unsigned)a);
            float hi = __uint_as_float((unsigned)(a >> 32));
            sm.red[(j * 32 + l) * (NC * 8) + c * 8 + w] = lo + hi;
        }
    __syncthreads();
    for (int o = t; o < NC * PT; o += 256) {
        int c = o >> 6, r = o & 63;
        const float4* v = (const float4*)&sm.red[r * (NC * 8) + c * 8];
        float4 a = v[0], b = v[1];
        g_qbf[n][blockIdx.y][c][pb + r] =
            ((a.x + a.y) + (a.z + a.w)) + ((b.x + b.y) + (b.z + b.w));
    }
}

__global__ void convy_kernel() {
    int t = blockIdx.x * 256 + threadIdx.x; // < NC*NP
    int n = blockIdx.y;
    int c = t >> 12, p = t & 4095;
    int y = p >> 6, x = p & 63;
    int j0 = max(0, y - RAD), j1 = min(63, y + RAD);
    const float* col = &g_q[n][c][x];
    float s = 0.f;
    for (int j = j0; j <= j1; j++) s = fmaf(g_g1[j - y + RAD], col[j * 64], s);
    g_tmp[n][c][p] = s;
}

__global__ void combine_kernel() {
    int t = blockIdx.x * 256 + threadIdx.x; // < NC*NP
    int n = blockIdx.y;
    int c = t >> 12, p = t & 4095;
    int y = p >> 6, x = p & 63;
    int j0 = max(0, x - RAD), j1 = min(63, x + RAD);
    const float* row = &g_tmp[n][c][y * 64];
    float s = 0.f;
    for (int j = j0; j <= j1; j++) s = fmaf(g_g1[j - x + RAD], row[j], s);
    float b = 0.f;
#pragma unroll
    for (int sl = 0; sl < QSPL; sl++) b += g_qbf[n][sl][c][p];
    g_comb[n][c][p] = fmaf(4.0f, b, 2.0f * s); // COMPAT_BF, COMPAT_SPATIAL
}

__global__ void fuse_kernel(float* __restrict__ dout, int last) {
    int t = blockIdx.x * 256 + threadIdx.x;
    if (t >= NB * NP) return;
    int n = t >> 12, p = t & 4095;
    float logit[NC]; float m = -1e30f;
#pragma unroll
    for (int c = 0; c < NC; c++) {
        float lg = g_U[n][c][p] + g_comb[n][c][p];
        logit[c] = lg; m = fmaxf(m, lg);
    }
    float sum = 0.f;
#pragma unroll
    for (int c = 0; c < NC; c++) { float e = __expf(logit[c] - m); logit[c] = e; sum += e; }
    float inv = 1.0f / sum;
#pragma unroll
    for (int c = 0; c < NC; c++) {
        float qq = logit[c] * inv;
        g_q[n][c][p] = qq;
        if (last) dout[(n * NC + c) * NP + p] = qq;
    }
}

extern "C" void kernel_launch(void* const* d_in, const int* in_sizes, int n_in,
                              void* d_out, int out_size) {
    const float* unary = (const float*)d_in[0];
    const float* ref   = (const float*)d_in[1];
    const float* gk    = (const float*)d_in[2];
    const float* kstd  = (const float*)d_in[3];
    float* dout = (float*)d_out;

    prep_kernel<<<32, 256>>>(unary, ref, kstd);
    g1_kernel<<<1, 128>>>(gk);
    buildk_kernel<<<dim3(64, 64, NB), 256>>>();
    for (int it = 0; it < 5; it++) {
        gemm_kernel<<<dim3(NP / PT, QSPL, NB), 256>>>();
        convy_kernel<<<dim3(336, NB), 256>>>();
        combine_kernel<<<dim3(336, NB), 256>>>();
        fuse_kernel<<<32, 256>>>(dout, it == 4);
    }
}

// round 11
// speedup vs baseline: 1.5637x; 1.1194x over previous
#include <cuda_runtime.h>
#include <math.h>

#define NB 2
#define NC 21
#define NP 4096
#define TAPS 71
#define RAD 35
#define MT 64
#define KS 8
#define KC (NP / KS)    // 512 q per CTA
#define QC 128          // q per chunk (128B u8 rows)
#define NCH (KC / QC)   // 4 chunks
#define BPB 144         // B tile pitch in bytes (bank-stagger)

__device__ unsigned char g_Khi[NB][NP][NP];   // 33.5MB
__device__ unsigned char g_Klo[NB][NP][NP];   // 33.5MB
__device__ float g_feat[NB][NP][8];
__device__ float g_U[NB][NC][NP];
__device__ float g_q[NB][NC][NP];
__device__ unsigned char g_qhi[NB][32][NP];   // rows 21..31 zero
__device__ unsigned char g_qlo[NB][32][NP];
__device__ float g_comb[NB][NC][NP];
__device__ float g_qbf[NB][KS][NC][NP];
__device__ float g_g1[TAPS];

__device__ __forceinline__ float fexp2(float t) {
    t = fmaxf(t, -120.0f);
    float z  = t + 12582912.0f;
    int   ei = __float_as_int(z) - 0x4B400000;
    float f  = t - (z - 12582912.0f);
    float p  = fmaf(f, 0.001333355814642f, 0.009618129107629f);
    p = fmaf(f, p, 0.055504108664822f);
    p = fmaf(f, p, 0.240226506959101f);
    p = fmaf(f, p, 0.693147180559945f);
    p = fmaf(f, p, 1.0f);
    return __int_as_float(__float_as_int(p) + (ei << 23));
}

__device__ __forceinline__ unsigned quant16(float v) {
    unsigned q = __float2uint_rn(v * 65535.f);
    return q > 65535u ? 65535u : q;
}

__global__ void prep_kernel(const float* __restrict__ unary,
                            const float* __restrict__ ref,
                            const float* __restrict__ kstd) {
    int t = blockIdx.x * 256 + threadIdx.x;
    if (t >= NB * NP) return;
    int n = t >> 12, p = t & (NP - 1);
    int y = p >> 6, x = p & 63;
    const float SQ = 1.2011224087864498f; // sqrt(log2 e)
    float f[5];
    f[0] = (float)y * (SQ / kstd[0]);
    f[1] = (float)x * (SQ / kstd[1]);
    f[2] = ref[(n * 3 + 0) * NP + p] * (SQ / kstd[2]);
    f[3] = ref[(n * 3 + 1) * NP + p] * (SQ / kstd[3]);
    f[4] = ref[(n * 3 + 2) * NP + p] * (SQ / kstd[4]);
    float a = 0.f;
#pragma unroll
    for (int k = 0; k < 5; k++) { g_feat[n][p][k] = f[k]; a = fmaf(f[k], f[k], a); }
    g_feat[n][p][5] = 0.5f * a;
    g_feat[n][p][6] = 0.f; g_feat[n][p][7] = 0.f;

    float pc[NC]; float s = 0.f;
#pragma unroll
    for (int c = 0; c < NC; c++) {
        float u = unary[(n * NC + c) * NP + p];
        u = fminf(fmaxf(u, 1e-5f), 1.0f);
        pc[c] = u; s += u;
        g_U[n][c][p] = logf(u);
    }
    float inv = 1.0f / s;
#pragma unroll
    for (int c = 0; c < NC; c++) {
        float q = pc[c] * inv;
        g_q[n][c][p] = q;
        unsigned Qq = quant16(q);
        g_qhi[n][c][p] = (unsigned char)(Qq >> 8);
        g_qlo[n][c][p] = (unsigned char)(Qq & 255u);
    }
#pragma unroll
    for (int c = NC; c < 32; c++) { g_qhi[n][c][p] = 0; g_qlo[n][c][p] = 0; }
}

// gk = outer(r, r) with r = row sums (exact separable factor)
__global__ void g1_kernel(const float* __restrict__ gk) {
    int t = threadIdx.x;
    if (t < TAPS) {
        float s = 0.f;
        for (int j = 0; j < TAPS; j++) s += gk[t * TAPS + j];
        g_g1[t] = s;
    }
}

__global__ __launch_bounds__(256) void buildk_kernel() {
    __shared__ float fp[64][8];
    __shared__ float fq[64][8];
    int n = blockIdx.z;
    int P0 = blockIdx.y * 64, Q0 = blockIdx.x * 64;
    for (int i = threadIdx.x; i < 64 * 8; i += 256) {
        int r = i >> 3, k = i & 7;
        fp[r][k] = g_feat[n][P0 + r][k];
        fq[r][k] = g_feat[n][Q0 + r][k];
    }
    __syncthreads();
    int ql = threadIdx.x & 63;
    int pg = threadIdx.x >> 6;
    float q0 = fq[ql][0], q1 = fq[ql][1], q2 = fq[ql][2];
    float q3 = fq[ql][3], q4 = fq[ql][4], qa = fq[ql][5];
#pragma unroll
    for (int k = 0; k < 16; k++) {
        int pl = pg * 16 + k;
        float4 a4 = *(const float4*)&fp[pl][0];
        float2 a2 = *(const float2*)&fp[pl][4];
        float acc = -(a2.y + qa);
        acc = fmaf(a4.x, q0, acc);
        acc = fmaf(a4.y, q1, acc);
        acc = fmaf(a4.z, q2, acc);
        acc = fmaf(a4.w, q3, acc);
        acc = fmaf(a2.x, q4, acc);
        // clamp: d2 >= 0 (matches reference's max(d2,0)); prevents 65536 wrap
        unsigned Kq = quant16(fexp2(fminf(acc, 0.f)));
        g_Khi[n][P0 + pl][Q0 + ql] = (unsigned char)(Kq >> 8);
        g_Klo[n][P0 + pl][Q0 + ql] = (unsigned char)(Kq & 255u);
    }
}

// u8-pair integer GEMM: D[64 p, 24 c] over 512-q slice, 128-q chunks.
// Exact s32 accumulate; K = Khi*256+Klo, q = qhi*256+qlo (16-bit fixed).
__global__ __launch_bounds__(128, 4) void gemm_mma_kernel() {
    __shared__ __align__(16) unsigned char sA[2][2][MT * QC];  // 2 buf x 2 plane x 8KB
    __shared__ __align__(16) unsigned char sB[2][2][24 * BPB];
    int n = blockIdx.z, ksb = blockIdx.y;
    int pb = blockIdx.x * MT;
    int k0 = ksb * KC;
    int t = threadIdx.x, w = t >> 5, l = t & 31;

#define PREFETCH(CH) do {                                                     \
        if ((CH) < NCH) {                                                     \
            int buf_ = (CH) & 1;                                              \
            int q0_ = k0 + (CH) * QC;                                         \
            _Pragma("unroll")                                                 \
            for (int i_ = 0; i_ < 8; i_++) {                                  \
                int seg_ = i_ * 128 + t;        /* < 1024 */                  \
                int pl_ = seg_ >> 9;                                          \
                int row_ = (seg_ >> 3) & 63, gi_ = seg_ & 7;                  \
                const unsigned char* gp_ = pl_ ?                              \
                    &g_Klo[n][pb + row_][q0_ + gi_ * 16] :                    \
                    &g_Khi[n][pb + row_][q0_ + gi_ * 16];                     \
                unsigned sa_ = (unsigned)__cvta_generic_to_shared(            \
                    &sA[buf_][pl_][row_ * QC + ((gi_ ^ (row_ & 7)) << 4)]);   \
                asm volatile("cp.async.cg.shared.global [%0], [%1], 16;"      \
                             :: "r"(sa_), "l"(gp_));                          \
            }                                                                 \
            _Pragma("unroll")                                                 \
            for (int i_ = 0; i_ < 3; i_++) {                                  \
                int seg_ = i_ * 128 + t;        /* < 384 */                   \
                if (seg_ < 384) {                                             \
                    int pl_ = seg_ / 192;                                     \
                    int row_ = (seg_ % 192) >> 3, gi_ = seg_ & 7;             \
                    const unsigned char* gp_ = pl_ ?                          \
                        &g_qlo[n][row_][q0_ + gi_ * 16] :                     \
                        &g_qhi[n][row_][q0_ + gi_ * 16];                      \
                    unsigned sa_ = (unsigned)__cvta_generic_to_shared(        \
                        &sB[buf_][pl_][row_ * BPB + gi_ * 16]);               \
                    asm volatile("cp.async.cg.shared.global [%0], [%1], 16;"  \
                                 :: "r"(sa_), "l"(gp_));                      \
                }                                                             \
            }                                                                 \
        }                                                                     \
        asm volatile("cp.async.commit_group;");                               \
    } while (0)

    int dhh[3][4], dmid[3][4], dll[3][4];
#pragma unroll
    for (int nt = 0; nt < 3; nt++)
#pragma unroll
        for (int j = 0; j < 4; j++) { dhh[nt][j] = 0; dmid[nt][j] = 0; dll[nt][j] = 0; }

    int mrow = w * 16 + (l & 7) + ((l >> 3) & 1) * 8;
    int ghalf = l >> 4;

    PREFETCH(0);
#pragma unroll 1
    for (int ch = 0; ch < NCH; ch++) {
        PREFETCH(ch + 1);
        asm volatile("cp.async.wait_group 1;");
        __syncthreads();
        int buf = ch & 1;
        const unsigned char* Ah = sA[buf][0];
        const unsigned char* Al = sA[buf][1];
        const unsigned char* Bh = sB[buf][0];
        const unsigned char* Bl = sB[buf][1];
#pragma unroll
        for (int ks = 0; ks < 4; ks++) {
            int g = ks * 2 + ghalf;
            int aoff = mrow * QC + ((g ^ (mrow & 7)) << 4);
            unsigned ah0, ah1, ah2, ah3, al0, al1, al2, al3;
            unsigned aaddr = (unsigned)__cvta_generic_to_shared(&Ah[aoff]);
            asm volatile("ldmatrix.sync.aligned.m8n8.x4.shared.b16 {%0,%1,%2,%3}, [%4];"
                         : "=r"(ah0), "=r"(ah1), "=r"(ah2), "=r"(ah3) : "r"(aaddr));
            aaddr = (unsigned)__cvta_generic_to_shared(&Al[aoff]);
            asm volatile("ldmatrix.sync.aligned.m8n8.x4.shared.b16 {%0,%1,%2,%3}, [%4];"
                         : "=r"(al0), "=r"(al1), "=r"(al2), "=r"(al3) : "r"(aaddr));
            int kb = ks * 32 + (l & 3) * 4;
#pragma unroll
            for (int nt = 0; nt < 3; nt++) {
                int nn = nt * 8 + (l >> 2);
                unsigned bh0 = *(const unsigned*)&Bh[nn * BPB + kb];
                unsigned bh1 = *(const unsigned*)&Bh[nn * BPB + kb + 16];
                unsigned bl0 = *(const unsigned*)&Bl[nn * BPB + kb];
                unsigned bl1 = *(const unsigned*)&Bl[nn * BPB + kb + 16];
#define MMA_U8(D, A0, A1, A2, A3, B0, B1)                                     \
                asm volatile(                                                 \
                    "mma.sync.aligned.m16n8k32.row.col.s32.u8.u8.s32 "        \
                    "{%0,%1,%2,%3}, {%4,%5,%6,%7}, {%8,%9}, {%0,%1,%2,%3};"   \
                    : "+r"(D[nt][0]), "+r"(D[nt][1]), "+r"(D[nt][2]), "+r"(D[nt][3]) \
                    : "r"(A0), "r"(A1), "r"(A2), "r"(A3), "r"(B0), "r"(B1))
                MMA_U8(dhh,  ah0, ah1, ah2, ah3, bh0, bh1);
                MMA_U8(dmid, ah0, ah1, ah2, ah3, bl0, bl1);
                MMA_U8(dmid, al0, al1, al2, al3, bh0, bh1);
                MMA_U8(dll,  al0, al1, al2, al3, bl0, bl1);
#undef MMA_U8
            }
        }
        __syncthreads();
    }
#undef PREFETCH

    const float INV = (float)(1.0 / (65535.0 * 65535.0));
#pragma unroll
    for (int nt = 0; nt < 3; nt++)
#pragma unroll
        for (int j = 0; j < 4; j++) {
            int col = nt * 8 + (l & 3) * 2 + (j & 1);
            int prow = pb + w * 16 + (l >> 2) + ((j >> 1) ? 8 : 0);
            if (col < NC) {
                float v = fmaf(65536.f, (float)dhh[nt][j],
                          fmaf(256.f, (float)dmid[nt][j], (float)dll[nt][j]));
                g_qbf[n][ksb][col][prow] = v * INV;
            }
        }
}

// fused separable conv (y then x) + qbf partial sum + compatibility, per plane quarter
__global__ __launch_bounds__(256) void convcomb_kernel() {
    __shared__ float sq[NP];     // full 64x64 plane
    __shared__ float st[1024];   // 16 rows of convy output
    __shared__ float sg[TAPS];
    int c = blockIdx.x, n = blockIdx.y, y0 = blockIdx.z * 16;
    int t = threadIdx.x;
    if (t < TAPS) sg[t] = g_g1[t];
    const float4* src = (const float4*)&g_q[n][c][0];
    float4* dq = (float4*)sq;
    for (int i = t; i < NP / 4; i += 256) dq[i] = src[i];
    __syncthreads();
#pragma unroll
    for (int i = 0; i < 4; i++) {
        int p = i * 256 + t;
        int y = y0 + (p >> 6), x = p & 63;
        int j0 = max(0, y - RAD), j1 = min(63, y + RAD);
        float s = 0.f;
        for (int j = j0; j <= j1; j++) s = fmaf(sg[j - y + RAD], sq[j * 64 + x], s);
        st[p] = s;
    }
    __syncthreads();
#pragma unroll
    for (int i = 0; i < 4; i++) {
        int p = i * 256 + t;
        int ly = p >> 6, x = p & 63;
        int j0 = max(0, x - RAD), j1 = min(63, x + RAD);
        const float* row = &st[ly * 64];
        float s = 0.f;
        for (int j = j0; j <= j1; j++) s = fmaf(sg[j - x + RAD], row[j], s);
        int gp = (y0 + ly) * 64 + x;
        float b = 0.f;
#pragma unroll
        for (int sl = 0; sl < KS; sl++) b += g_qbf[n][sl][c][gp];
        g_comb[n][c][gp] = fmaf(4.0f, b, 2.0f * s); // COMPAT_BF, COMPAT_SPATIAL
    }
}

__global__ void fuse_kernel(float* __restrict__ dout, int last) {
    int t = blockIdx.x * 256 + threadIdx.x;
    if (t >= NB * NP) return;
    int n = t >> 12, p = t & 4095;
    float logit[NC]; float m = -1e30f;
#pragma unroll
    for (int c = 0; c < NC; c++) {
        float lg = g_U[n][c][p] + g_comb[n][c][p];
        logit[c] = lg; m = fmaxf(m, lg);
    }
    float sum = 0.f;
#pragma unroll
    for (int c = 0; c < NC; c++) { float e = __expf(logit[c] - m); logit[c] = e; sum += e; }
    float inv = 1.0f / sum;
#pragma unroll
    for (int c = 0; c < NC; c++) {
        float qq = logit[c] * inv;
        g_q[n][c][p] = qq;
        unsigned Qq = quant16(qq);
        g_qhi[n][c][p] = (unsigned char)(Qq >> 8);
        g_qlo[n][c][p] = (unsigned char)(Qq & 255u);
        if (last) dout[(n * NC + c) * NP + p] = qq;
    }
}

extern "C" void kernel_launch(void* const* d_in, const int* in_sizes, int n_in,
                              void* d_out, int out_size) {
    const float* unary = (const float*)d_in[0];
    const float* ref   = (const float*)d_in[1];
    const float* gk    = (const float*)d_in[2];
    const float* kstd  = (const float*)d_in[3];
    float* dout = (float*)d_out;

    prep_kernel<<<32, 256>>>(unary, ref, kstd);
    g1_kernel<<<1, 128>>>(gk);
    buildk_kernel<<<dim3(64, 64, NB), 256>>>();
    for (int it = 0; it < 5; it++) {
        gemm_mma_kernel<<<dim3(NP / MT, KS, NB), 128>>>();
        convcomb_kernel<<<dim3(NC, NB, 4), 256>>>();
        fuse_kernel<<<32, 256>>>(dout, it == 4);
    }
}

// round 13
// speedup vs baseline: 1.7449x; 1.1159x over previous
#include <cuda_runtime.h>
#include <math.h>

#define NB 2
#define NC 21
#define NP 4096
#define TAPS 71
#define RAD 35
#define MT 64
#define KS 8
#define KC (NP / KS)    // 512 q per CTA
#define QC 128          // q per chunk (128B u8 rows)
#define NCH (KC / QC)   // 4 chunks
#define BPB 144         // B tile pitch in bytes (bank-stagger)
#define NCONV (NC * NB * 8)   // 336 conv blocks (8-row slabs)
#define NGEMM ((NP / MT) * KS * NB)  // 1024 gemm blocks

__device__ unsigned char g_Khi[NB][NP][NP];   // 33.5MB
__device__ unsigned char g_Klo[NB][NP][NP];   // 33.5MB
__device__ float g_feat[NB][NP][8];
__device__ float g_U[NB][NC][NP];
__device__ float g_q[NB][NC][NP];
__device__ unsigned char g_qhi[NB][32][NP];   // rows 21..31 zero
__device__ unsigned char g_qlo[NB][32][NP];
__device__ float g_comb[NB][NC][NP];          // raw spatial conv result
__device__ float g_qbf[NB][KS][NC][NP];
__device__ float g_g1[TAPS];

struct GemmSm { unsigned char A[4][MT * QC]; unsigned char B[4][24 * BPB]; };
struct ConvSm { float sq[NP]; float st[512]; float sg[TAPS]; };
union WorkSm { GemmSm g; ConvSm c; };

__device__ __forceinline__ float fexp2(float t) {
    t = fmaxf(t, -120.0f);
    float z  = t + 12582912.0f;
    int   ei = __float_as_int(z) - 0x4B400000;
    float f  = t - (z - 12582912.0f);
    float p  = fmaf(f, 0.001333355814642f, 0.009618129107629f);
    p = fmaf(f, p, 0.055504108664822f);
    p = fmaf(f, p, 0.240226506959101f);
    p = fmaf(f, p, 0.693147180559945f);
    p = fmaf(f, p, 1.0f);
    return __int_as_float(__float_as_int(p) + (ei << 23));
}

__device__ __forceinline__ unsigned quant16(float v) {
    unsigned q = __float2uint_rn(v * 65535.f);
    return q > 65535u ? 65535u : q;
}

__global__ void prep_kernel(const float* __restrict__ unary,
                            const float* __restrict__ ref,
                            const float* __restrict__ kstd) {
    int t = blockIdx.x * 256 + threadIdx.x;
    if (t >= NB * NP) return;
    int n = t >> 12, p = t & (NP - 1);
    int y = p >> 6, x = p & 63;
    const float SQ = 1.2011224087864498f; // sqrt(log2 e)
    float f[5];
    f[0] = (float)y * (SQ / kstd[0]);
    f[1] = (float)x * (SQ / kstd[1]);
    f[2] = ref[(n * 3 + 0) * NP + p] * (SQ / kstd[2]);
    f[3] = ref[(n * 3 + 1) * NP + p] * (SQ / kstd[3]);
    f[4] = ref[(n * 3 + 2) * NP + p] * (SQ / kstd[4]);
    float a = 0.f;
#pragma unroll
    for (int k = 0; k < 5; k++) { g_feat[n][p][k] = f[k]; a = fmaf(f[k], f[k], a); }
    g_feat[n][p][5] = 0.5f * a;
    g_feat[n][p][6] = 0.f; g_feat[n][p][7] = 0.f;

    float pc[NC]; float s = 0.f;
#pragma unroll
    for (int c = 0; c < NC; c++) {
        float u = unary[(n * NC + c) * NP + p];
        u = fminf(fmaxf(u, 1e-5f), 1.0f);
        pc[c] = u; s += u;
        g_U[n][c][p] = logf(u);
    }
    float inv = 1.0f / s;
#pragma unroll
    for (int c = 0; c < NC; c++) {
        float q = pc[c] * inv;
        g_q[n][c][p] = q;
        unsigned Qq = quant16(q);
        g_qhi[n][c][p] = (unsigned char)(Qq >> 8);
        g_qlo[n][c][p] = (unsigned char)(Qq & 255u);
    }
#pragma unroll
    for (int c = NC; c < 32; c++) { g_qhi[n][c][p] = 0; g_qlo[n][c][p] = 0; }
}

// gk = outer(r, r) with r = row sums (exact separable factor)
__global__ void g1_kernel(const float* __restrict__ gk) {
    int t = threadIdx.x;
    if (t < TAPS) {
        float s = 0.f;
        for (int j = 0; j < TAPS; j++) s += gk[t * TAPS + j];
        g_g1[t] = s;
    }
}

__global__ __launch_bounds__(256) void buildk_kernel() {
    __shared__ float fp[64][8];
    __shared__ float fq[64][8];
    int n = blockIdx.z;
    int P0 = blockIdx.y * 64, Q0 = blockIdx.x * 64;
    for (int i = threadIdx.x; i < 64 * 8; i += 256) {
        int r = i >> 3, k = i & 7;
        fp[r][k] = g_feat[n][P0 + r][k];
        fq[r][k] = g_feat[n][Q0 + r][k];
    }
    __syncthreads();
    int ql = threadIdx.x & 63;
    int pg = threadIdx.x >> 6;
    float q0 = fq[ql][0], q1 = fq[ql][1], q2 = fq[ql][2];
    float q3 = fq[ql][3], q4 = fq[ql][4], qa = fq[ql][5];
#pragma unroll
    for (int k = 0; k < 16; k++) {
        int pl = pg * 16 + k;
        float4 a4 = *(const float4*)&fp[pl][0];
        float2 a2 = *(const float2*)&fp[pl][4];
        float acc = -(a2.y + qa);
        acc = fmaf(a4.x, q0, acc);
        acc = fmaf(a4.y, q1, acc);
        acc = fmaf(a4.z, q2, acc);
        acc = fmaf(a4.w, q3, acc);
        acc = fmaf(a2.x, q4, acc);
        // clamp: d2 >= 0 (matches reference's max(d2,0)); prevents 65536 wrap
        unsigned Kq = quant16(fexp2(fminf(acc, 0.f)));
        g_Khi[n][P0 + pl][Q0 + ql] = (unsigned char)(Kq >> 8);
        g_Klo[n][P0 + pl][Q0 + ql] = (unsigned char)(Kq & 255u);
    }
}

// ---- conv branch: separable 71-tap conv on one (n,c) plane, 8-row slab ----
__device__ __forceinline__ void conv_body(ConvSm& s, int cid) {
    int t = threadIdx.x;
    int c = cid % NC;
    int rem = cid / NC;
    int n = rem & 1;
    int y0 = (rem >> 1) * 8;
    if (t < TAPS) s.sg[t] = g_g1[t];
    const float4* src = (const float4*)&g_q[n][c][0];
    float4* dq = (float4*)s.sq;
#pragma unroll
    for (int i = 0; i < 8; i++) dq[i * 128 + t] = src[i * 128 + t];
    __syncthreads();
#pragma unroll
    for (int i = 0; i < 4; i++) {
        int p = i * 128 + t;              // 0..511
        int y = y0 + (p >> 6), x = p & 63;
        int j0 = max(0, y - RAD), j1 = min(63, y + RAD);
        float acc = 0.f;
        for (int j = j0; j <= j1; j++) acc = fmaf(s.sg[j - y + RAD], s.sq[j * 64 + x], acc);
        s.st[p] = acc;
    }
    __syncthreads();
#pragma unroll
    for (int i = 0; i < 4; i++) {
        int p = i * 128 + t;
        int ly = p >> 6, x = p & 63;
        int j0 = max(0, x - RAD), j1 = min(63, x + RAD);
        float acc = 0.f;
        for (int j = j0; j <= j1; j++) acc = fmaf(s.sg[j - x + RAD], s.st[ly * 64 + j], acc);
        g_comb[n][c][(y0 + ly) * 64 + x] = acc;   // raw spatial conv
    }
}

// ---- gemm branch: u8-pair integer MMA, D[64 p, 24 c] over 512-q slice ----
__device__ __forceinline__ void gemm_body(GemmSm& s, int gid) {
    int n = gid >> 9;
    int ksb = (gid >> 6) & 7;
    int pb = (gid & 63) * MT;
    int k0 = ksb * KC;
    int t = threadIdx.x, w = t >> 5, l = t & 31;

#define PREFETCH(CH) do {                                                     \
        if ((CH) < NCH) {                                                     \
            int buf_ = (CH) & 1;                                              \
            int q0_ = k0 + (CH) * QC;                                         \
            _Pragma("unroll")                                                 \
            for (int i_ = 0; i_ < 8; i_++) {                                  \
                int seg_ = i_ * 128 + t;        /* < 1024 */                  \
                int pl_ = seg_ >> 9;                                          \
                int row_ = (seg_ >> 3) & 63, gi_ = seg_ & 7;                  \
                const unsigned char* gp_ = pl_ ?                              \
                    &g_Klo[n][pb + row_][q0_ + gi_ * 16] :                    \
                    &g_Khi[n][pb + row_][q0_ + gi_ * 16];                     \
                unsigned sa_ = (unsigned)__cvta_generic_to_shared(            \
                    &s.A[buf_ * 2 + pl_][row_ * QC + ((gi_ ^ (row_ & 7)) << 4)]); \
                asm volatile("cp.async.cg.shared.global [%0], [%1], 16;"      \
                             :: "r"(sa_), "l"(gp_));                          \
            }                                                                 \
            _Pragma("unroll")                                                 \
            for (int i_ = 0; i_ < 3; i_++) {                                  \
                int seg_ = i_ * 128 + t;        /* < 384 */                   \
                if (seg_ < 384) {                                             \
                    int pl_ = seg_ / 192;                                     \
                    int row_ = (seg_ % 192) >> 3, gi_ = seg_ & 7;             \
                    const unsigned char* gp_ = pl_ ?                          \
                        &g_qlo[n][row_][q0_ + gi_ * 16] :                     \
                        &g_qhi[n][row_][q0_ + gi_ * 16];                      \
                    unsigned sa_ = (unsigned)__cvta_generic_to_shared(        \
                        &s.B[buf_ * 2 + pl_][row_ * BPB + gi_ * 16]);         \
                    asm volatile("cp.async.cg.shared.global [%0], [%1], 16;"  \
                                 :: "r"(sa_), "l"(gp_));                      \
                }                                                             \
            }                                                                 \
        }                                                                     \
        asm volatile("cp.async.commit_group;");                               \
    } while (0)

    int dhh[3][4], dmid[3][4], dll[3][4];
#pragma unroll
    for (int nt = 0; nt < 3; nt++)
#pragma unroll
        for (int j = 0; j < 4; j++) { dhh[nt][j] = 0; dmid[nt][j] = 0; dll[nt][j] = 0; }

    int mrow = w * 16 + (l & 7) + ((l >> 3) & 1) * 8;
    int ghalf = l >> 4;

    PREFETCH(0);
#pragma unroll 1
    for (int ch = 0; ch < NCH; ch++) {
        PREFETCH(ch + 1);
        asm volatile("cp.async.wait_group 1;");
        __syncthreads();
        int buf = ch & 1;
        const unsigned char* Ah = s.A[buf * 2 + 0];
        const unsigned char* Al = s.A[buf * 2 + 1];
        const unsigned char* Bh = s.B[buf * 2 + 0];
        const unsigned char* Bl = s.B[buf * 2 + 1];
#pragma unroll
        for (int ks = 0; ks < 4; ks++) {
            int g = ks * 2 + ghalf;
            int aoff = mrow * QC + ((g ^ (mrow & 7)) << 4);
            unsigned ah0, ah1, ah2, ah3, al0, al1, al2, al3;
            unsigned aaddr = (unsigned)__cvta_generic_to_shared(&Ah[aoff]);
            asm volatile("ldmatrix.sync.aligned.m8n8.x4.shared.b16 {%0,%1,%2,%3}, [%4];"
                         : "=r"(ah0), "=r"(ah1), "=r"(ah2), "=r"(ah3) : "r"(aaddr));
            aaddr = (unsigned)__cvta_generic_to_shared(&Al[aoff]);
            asm volatile("ldmatrix.sync.aligned.m8n8.x4.shared.b16 {%0,%1,%2,%3}, [%4];"
                         : "=r"(al0), "=r"(al1), "=r"(al2), "=r"(al3) : "r"(aaddr));
            int kb = ks * 32 + (l & 3) * 4;
#pragma unroll
            for (int nt = 0; nt < 3; nt++) {
                int nn = nt * 8 + (l >> 2);
                unsigned bh0 = *(const unsigned*)&Bh[nn * BPB + kb];
                unsigned bh1 = *(const unsigned*)&Bh[nn * BPB + kb + 16];
                unsigned bl0 = *(const unsigned*)&Bl[nn * BPB + kb];
                unsigned bl1 = *(const unsigned*)&Bl[nn * BPB + kb + 16];
#define MMA_U8(D, A0, A1, A2, A3, B0, B1)                                     \
                asm volatile(                                                 \
                    "mma.sync.aligned.m16n8k32.row.col.s32.u8.u8.s32 "        \
                    "{%0,%1,%2,%3}, {%4,%5,%6,%7}, {%8,%9}, {%0,%1,%2,%3};"   \
                    : "+r"(D[nt][0]), "+r"(D[nt][1]), "+r"(D[nt][2]), "+r"(D[nt][3]) \
                    : "r"(A0), "r"(A1), "r"(A2), "r"(A3), "r"(B0), "r"(B1))
                MMA_U8(dhh,  ah0, ah1, ah2, ah3, bh0, bh1);
                MMA_U8(dmid, ah0, ah1, ah2, ah3, bl0, bl1);
                MMA_U8(dmid, al0, al1, al2, al3, bh0, bh1);
                MMA_U8(dll,  al0, al1, al2, al3, bl0, bl1);
#undef MMA_U8
            }
        }
        __syncthreads();
    }
#undef PREFETCH

    const float INV = (float)(1.0 / (65535.0 * 65535.0));
#pragma unroll
    for (int nt = 0; nt < 3; nt++)
#pragma unroll
        for (int j = 0; j < 4; j++) {
            int col = nt * 8 + (l & 3) * 2 + (j & 1);
            int prow = pb + w * 16 + (l >> 2) + ((j >> 1) ? 8 : 0);
            if (col < NC) {
                float v = fmaf(65536.f, (float)dhh[nt][j],
                          fmaf(256.f, (float)dmid[nt][j], (float)dll[nt][j]));
                g_qbf[n][ksb][col][prow] = v * INV;
            }
        }
}

// heterogeneous grid: first NCONV blocks do spatial conv (fma/lds pipes),
// remaining NGEMM blocks do the tensor-pipe GEMM — complementary overlap.
__global__ __launch_bounds__(128) void work_kernel() {
    __shared__ WorkSm sm;
    int b = blockIdx.x;
    if (b < NCONV) conv_body(sm.c, b);
    else           gemm_body(sm.g, b - NCONV);
}

// combine (8 qbf slices + spatial) + compatibility + softmax + u8 re-pack
__global__ void fuse2_kernel(float* __restrict__ dout, int last) {
    int t = blockIdx.x * 256 + threadIdx.x;
    if (t >= NB * NP) return;
    int n = t >> 12, p = t & 4095;
    float logit[NC]; float m = -1e30f;
#pragma unroll
    for (int c = 0; c < NC; c++) {
        float b8 = 0.f;
#pragma unroll
        for (int sl = 0; sl < KS; sl++) b8 += g_qbf[n][sl][c][p];
        float s = g_comb[n][c][p];
        float lg = g_U[n][c][p] + fmaf(4.0f, b8, 2.0f * s); // COMPAT_BF, COMPAT_SPATIAL
        logit[c] = lg; m = fmaxf(m, lg);
    }
    float sum = 0.f;
#pragma unroll
    for (int c = 0; c < NC; c++) { float e = __expf(logit[c] - m); logit[c] = e; sum += e; }
    float inv = 1.0f / sum;
#pragma unroll
    for (int c = 0; c < NC; c++) {
        float qq = logit[c] * inv;
        g_q[n][c][p] = qq;
        unsigned Qq = quant16(qq);
        g_qhi[n][c][p] = (unsigned char)(Qq >> 8);
        g_qlo[n][c][p] = (unsigned char)(Qq & 255u);
        if (last) dout[(n * NC + c) * NP + p] = qq;
    }
}

extern "C" void kernel_launch(void* const* d_in, const int* in_sizes, int n_in,
                              void* d_out, int out_size) {
    const float* unary = (const float*)d_in[0];
    const float* ref   = (const float*)d_in[1];
    const float* gk    = (const float*)d_in[2];
    const float* kstd  = (const float*)d_in[3];
    float* dout = (float*)d_out;

    prep_kernel<<<32, 256>>>(unary, ref, kstd);
    g1_kernel<<<1, 128>>>(gk);
    buildk_kernel<<<dim3(64, 64, NB), 256>>>();
    for (int it = 0; it < 5; it++) {
        work_kernel<<<NCONV + NGEMM, 128>>>();
        fuse2_kernel<<<32, 256>>>(dout, it == 4);
    }
}

// round 14
// speedup vs baseline: 1.7635x; 1.0107x over previous
#include <cuda_runtime.h>
#include <math.h>

#define NB 2
#define NC 21
#define NP 4096
#define TAPS 71
#define RAD 35
#define MT 64
#define KS 8
#define KC (NP / KS)    // 512 q per CTA
#define QC 128          // q per chunk (128B u8 rows)
#define NCH (KC / QC)   // 4 chunks
#define BPB 144         // B tile pitch in bytes (bank-stagger)
#define NCONV (NC * NB * 8)          // 336 conv blocks
#define NGEMM ((NP / MT) * KS * NB)  // 1024 gemm blocks
#define NSUM (NB * KS * NC)          // 336 qlo-sum blocks

__device__ unsigned char g_Khi[NB][NP][NP];   // 33.5MB
__device__ unsigned char g_Klo[NB][NP][NP];   // 33.5MB
__device__ float g_feat[NB][NP][8];
__device__ float g_U[NB][NC][NP];
__device__ float g_q[NB][NC][NP];
__device__ unsigned char g_qhi[NB][32][NP];   // rows 21..31 zero
__device__ unsigned char g_qlo[NB][32][NP];
__device__ float g_comb[NB][NC][NP];          // raw spatial conv result
__device__ float g_qbf[NB][KS][NC][NP];
__device__ float g_klosum[NB][KS][NP];        // per-slice row sums of Klo (fixed)
__device__ unsigned g_qlosumcur[NB][KS][NC];  // per-slice qlo sums (this iter's q)
__device__ float g_g1[TAPS];

struct GemmSm { unsigned char A[4][MT * QC]; unsigned char B[4][24 * BPB]; };
struct ConvSm { float sq[NP]; float st[512]; float sg[TAPS]; };
union WorkSm { GemmSm g; ConvSm c; };

__device__ __forceinline__ float fexp2(float t) {
    t = fmaxf(t, -120.0f);
    float z  = t + 12582912.0f;
    int   ei = __float_as_int(z) - 0x4B400000;
    float f  = t - (z - 12582912.0f);
    float p  = fmaf(f, 0.001333355814642f, 0.009618129107629f);
    p = fmaf(f, p, 0.055504108664822f);
    p = fmaf(f, p, 0.240226506959101f);
    p = fmaf(f, p, 0.693147180559945f);
    p = fmaf(f, p, 1.0f);
    return __int_as_float(__float_as_int(p) + (ei << 23));
}

__device__ __forceinline__ unsigned quant16(float v) {
    unsigned q = __float2uint_rn(v * 65535.f);
    return q > 65535u ? 65535u : q;
}

__global__ void prep_kernel(const float* __restrict__ unary,
                            const float* __restrict__ ref,
                            const float* __restrict__ kstd) {
    int t = blockIdx.x * 256 + threadIdx.x;
    if (t >= NB * NP) return;
    int n = t >> 12, p = t & (NP - 1);
    int y = p >> 6, x = p & 63;
    const float SQ = 1.2011224087864498f; // sqrt(log2 e)
    float f[5];
    f[0] = (float)y * (SQ / kstd[0]);
    f[1] = (float)x * (SQ / kstd[1]);
    f[2] = ref[(n * 3 + 0) * NP + p] * (SQ / kstd[2]);
    f[3] = ref[(n * 3 + 1) * NP + p] * (SQ / kstd[3]);
    f[4] = ref[(n * 3 + 2) * NP + p] * (SQ / kstd[4]);
    float a = 0.f;
#pragma unroll
    for (int k = 0; k < 5; k++) { g_feat[n][p][k] = f[k]; a = fmaf(f[k], f[k], a); }
    g_feat[n][p][5] = 0.5f * a;
    g_feat[n][p][6] = 0.f; g_feat[n][p][7] = 0.f;

    float pc[NC]; float s = 0.f;
#pragma unroll
    for (int c = 0; c < NC; c++) {
        float u = unary[(n * NC + c) * NP + p];
        u = fminf(fmaxf(u, 1e-5f), 1.0f);
        pc[c] = u; s += u;
        g_U[n][c][p] = logf(u);
    }
    float inv = 1.0f / s;
#pragma unroll
    for (int c = 0; c < NC; c++) {
        float q = pc[c] * inv;
        g_q[n][c][p] = q;
        unsigned Qq = quant16(q);
        g_qhi[n][c][p] = (unsigned char)(Qq >> 8);
        g_qlo[n][c][p] = (unsigned char)(Qq & 255u);
    }
#pragma unroll
    for (int c = NC; c < 32; c++) { g_qhi[n][c][p] = 0; g_qlo[n][c][p] = 0; }
}

// gk = outer(r, r) with r = row sums (exact separable factor)
__global__ void g1_kernel(const float* __restrict__ gk) {
    int t = threadIdx.x;
    if (t < TAPS) {
        float s = 0.f;
        for (int j = 0; j < TAPS; j++) s += gk[t * TAPS + j];
        g_g1[t] = s;
    }
}

// symmetric K build: only upper-triangle tiles computed; both orientations
// written from an smem-staged u16 tile. Exact (K(p,q)=K(q,p)).
__global__ __launch_bounds__(256) void buildk_kernel() {
    __shared__ float fp[64][8];
    __shared__ float fq[64][8];
    __shared__ unsigned short tile[64][65];
    int n = blockIdx.z;
    int bi = blockIdx.y, bj = blockIdx.x;
    if (bj < bi) return;                 // lower triangle: exit immediately
    int P0 = bi * 64, Q0 = bj * 64;
    for (int i = threadIdx.x; i < 64 * 8; i += 256) {
        int r = i >> 3, k = i & 7;
        fp[r][k] = g_feat[n][P0 + r][k];
        fq[r][k] = g_feat[n][Q0 + r][k];
    }
    __syncthreads();
    int ql = threadIdx.x & 63;
    int pg = threadIdx.x >> 6;
    float q0 = fq[ql][0], q1 = fq[ql][1], q2 = fq[ql][2];
    float q3 = fq[ql][3], q4 = fq[ql][4], qa = fq[ql][5];
#pragma unroll
    for (int k = 0; k < 16; k++) {
        int pl = pg * 16 + k;
        float4 a4 = *(const float4*)&fp[pl][0];
        float2 a2 = *(const float2*)&fp[pl][4];
        float acc = -(a2.y + qa);
        acc = fmaf(a4.x, q0, acc);
        acc = fmaf(a4.y, q1, acc);
        acc = fmaf(a4.z, q2, acc);
        acc = fmaf(a4.w, q3, acc);
        acc = fmaf(a2.x, q4, acc);
        // clamp: d2 >= 0 (reference's max(d2,0)); prevents 65536 wrap
        tile[pl][ql] = (unsigned short)quant16(fexp2(fminf(acc, 0.f)));
    }
    __syncthreads();
    for (int idx = threadIdx.x; idx < 4096; idx += 256) {
        int r = idx >> 6, c = idx & 63;
        unsigned v = tile[r][c];
        g_Khi[n][P0 + r][Q0 + c] = (unsigned char)(v >> 8);
        g_Klo[n][P0 + r][Q0 + c] = (unsigned char)(v & 255u);
    }
    if (bi != bj) {
        for (int idx = threadIdx.x; idx < 4096; idx += 256) {
            int r = idx >> 6, c = idx & 63;
            unsigned v = tile[c][r];
            g_Khi[n][Q0 + r][P0 + c] = (unsigned char)(v >> 8);
            g_Klo[n][Q0 + r][P0 + c] = (unsigned char)(v & 255u);
        }
    }
}

// one-time: per-slice row sums of Klo (for dropped-ll compensation)
__global__ __launch_bounds__(256) void klosum_kernel() {
    int n = blockIdx.y;
    int p = blockIdx.x * 8 + (threadIdx.x >> 5);
    int l = threadIdx.x & 31;
    const unsigned* row = (const unsigned*)&g_Klo[n][p][0];
#pragma unroll
    for (int s = 0; s < 8; s++) {
        unsigned acc = 0;
#pragma unroll
        for (int i = 0; i < 4; i++)
            acc = __dp4a(row[s * 128 + i * 32 + l], 0x01010101u, acc);
#pragma unroll
        for (int o = 16; o; o >>= 1) acc += __shfl_xor_sync(0xFFFFFFFFu, acc, o);
        if (l == 0) g_klosum[n][s][p] = (float)acc;
    }
}

// ---- conv branch: separable 71-tap conv on one (n,c) plane, 8-row slab ----
__device__ __forceinline__ void conv_body(ConvSm& s, int cid) {
    int t = threadIdx.x;
    int c = cid % NC;
    int rem = cid / NC;
    int n = rem & 1;
    int y0 = (rem >> 1) * 8;
    if (t < TAPS) s.sg[t] = g_g1[t];
    const float4* src = (const float4*)&g_q[n][c][0];
    float4* dq = (float4*)s.sq;
#pragma unroll
    for (int i = 0; i < 8; i++) dq[i * 128 + t] = src[i * 128 + t];
    __syncthreads();
#pragma unroll
    for (int i = 0; i < 4; i++) {
        int p = i * 128 + t;              // 0..511
        int y = y0 + (p >> 6), x = p & 63;
        int j0 = max(0, y - RAD), j1 = min(63, y + RAD);
        float acc = 0.f;
        for (int j = j0; j <= j1; j++) acc = fmaf(s.sg[j - y + RAD], s.sq[j * 64 + x], acc);
        s.st[p] = acc;
    }
    __syncthreads();
#pragma unroll
    for (int i = 0; i < 4; i++) {
        int p = i * 128 + t;
        int ly = p >> 6, x = p & 63;
        int j0 = max(0, x - RAD), j1 = min(63, x + RAD);
        float acc = 0.f;
        for (int j = j0; j <= j1; j++) acc = fmaf(s.sg[j - x + RAD], s.st[ly * 64 + j], acc);
        g_comb[n][c][(y0 + ly) * 64 + x] = acc;   // raw spatial conv
    }
}

// ---- qlo per-slice/channel sums (for ll compensation; integer-exact) ----
__device__ __forceinline__ void qlosum_body(int sid) {
    __shared__ unsigned ws[4];
    int n = sid / (KS * NC);
    int rem = sid % (KS * NC);
    int sl = rem / NC, c = rem % NC;
    int t = threadIdx.x;
    unsigned v = ((const unsigned*)&g_qlo[n][c][sl * 512])[t];
    unsigned acc = __dp4a(v, 0x01010101u, 0u);
#pragma unroll
    for (int o = 16; o; o >>= 1) acc += __shfl_xor_sync(0xFFFFFFFFu, acc, o);
    if ((t & 31) == 0) ws[t >> 5] = acc;
    __syncthreads();
    if (t == 0) g_qlosumcur[n][sl][c] = ws[0] + ws[1] + ws[2] + ws[3];
}

// ---- gemm branch: u8-pair integer MMA, 3 chains (ll dropped, compensated) ----
__device__ __forceinline__ void gemm_body(GemmSm& s, int gid) {
    int n = gid >> 9;
    int ksb = (gid >> 6) & 7;
    int pb = (gid & 63) * MT;
    int k0 = ksb * KC;
    int t = threadIdx.x, w = t >> 5, l = t & 31;

#define PREFETCH(CH) do {                                                     \
        if ((CH) < NCH) {                                                     \
            int buf_ = (CH) & 1;                                              \
            int q0_ = k0 + (CH) * QC;                                         \
            _Pragma("unroll")                                                 \
            for (int i_ = 0; i_ < 8; i_++) {                                  \
                int seg_ = i_ * 128 + t;        /* < 1024 */                  \
                int pl_ = seg_ >> 9;                                          \
                int row_ = (seg_ >> 3) & 63, gi_ = seg_ & 7;                  \
                const unsigned char* gp_ = pl_ ?                              \
                    &g_Klo[n][pb + row_][q0_ + gi_ * 16] :                    \
                    &g_Khi[n][pb + row_][q0_ + gi_ * 16];                     \
                unsigned sa_ = (unsigned)__cvta_generic_to_shared(            \
                    &s.A[buf_ * 2 + pl_][row_ * QC + ((gi_ ^ (row_ & 7)) << 4)]); \
                asm volatile("cp.async.cg.shared.global [%0], [%1], 16;"      \
                             :: "r"(sa_), "l"(gp_));                          \
            }                                                                 \
            _Pragma("unroll")                                                 \
            for (int i_ = 0; i_ < 3; i_++) {                                  \
                int seg_ = i_ * 128 + t;        /* < 384 */                   \
                if (seg_ < 384) {                                             \
                    int pl_ = seg_ / 192;                                     \
                    int row_ = (seg_ % 192) >> 3, gi_ = seg_ & 7;             \
                    const unsigned char* gp_ = pl_ ?                          \
                        &g_qlo[n][row_][q0_ + gi_ * 16] :                     \
                        &g_qhi[n][row_][q0_ + gi_ * 16];                      \
                    unsigned sa_ = (unsigned)__cvta_generic_to_shared(        \
                        &s.B[buf_ * 2 + pl_][row_ * BPB + gi_ * 16]);         \
                    asm volatile("cp.async.cg.shared.global [%0], [%1], 16;"  \
                                 :: "r"(sa_), "l"(gp_));                      \
                }                                                             \
            }                                                                 \
        }                                                                     \
        asm volatile("cp.async.commit_group;");                               \
    } while (0)

    int dhh[3][4], dmid[3][4];
#pragma unroll
    for (int nt = 0; nt < 3; nt++)
#pragma unroll
        for (int j = 0; j < 4; j++) { dhh[nt][j] = 0; dmid[nt][j] = 0; }

    int mrow = w * 16 + (l & 7) + ((l >> 3) & 1) * 8;
    int ghalf = l >> 4;

    PREFETCH(0);
#pragma unroll 1
    for (int ch = 0; ch < NCH; ch++) {
        PREFETCH(ch + 1);
        asm volatile("cp.async.wait_group 1;");
        __syncthreads();
        int buf = ch & 1;
        const unsigned char* Ah = s.A[buf * 2 + 0];
        const unsigned char* Al = s.A[buf * 2 + 1];
        const unsigned char* Bh = s.B[buf * 2 + 0];
        const unsigned char* Bl = s.B[buf * 2 + 1];
#pragma unroll
        for (int ks = 0; ks < 4; ks++) {
            int g = ks * 2 + ghalf;
            int aoff = mrow * QC + ((g ^ (mrow & 7)) << 4);
            unsigned ah0, ah1, ah2, ah3, al0, al1, al2, al3;
            unsigned aaddr = (unsigned)__cvta_generic_to_shared(&Ah[aoff]);
            asm volatile("ldmatrix.sync.aligned.m8n8.x4.shared.b16 {%0,%1,%2,%3}, [%4];"
                         : "=r"(ah0), "=r"(ah1), "=r"(ah2), "=r"(ah3) : "r"(aaddr));
            aaddr = (unsigned)__cvta_generic_to_shared(&Al[aoff]);
            asm volatile("ldmatrix.sync.aligned.m8n8.x4.shared.b16 {%0,%1,%2,%3}, [%4];"
                         : "=r"(al0), "=r"(al1), "=r"(al2), "=r"(al3) : "r"(aaddr));
            int kb = ks * 32 + (l & 3) * 4;
#pragma unroll
            for (int nt = 0; nt < 3; nt++) {
                int nn = nt * 8 + (l >> 2);
                unsigned bh0 = *(const unsigned*)&Bh[nn * BPB + kb];
                unsigned bh1 = *(const unsigned*)&Bh[nn * BPB + kb + 16];
                unsigned bl0 = *(const unsigned*)&Bl[nn * BPB + kb];
                unsigned bl1 = *(const unsigned*)&Bl[nn * BPB + kb + 16];
#define MMA_U8(D, A0, A1, A2, A3, B0, B1)                                     \
                asm volatile(                                                 \
                    "mma.sync.aligned.m16n8k32.row.col.s32.u8.u8.s32 "        \
                    "{%0,%1,%2,%3}, {%4,%5,%6,%7}, {%8,%9}, {%0,%1,%2,%3};"   \
                    : "+r"(D[nt][0]), "+r"(D[nt][1]), "+r"(D[nt][2]), "+r"(D[nt][3]) \
                    : "r"(A0), "r"(A1), "r"(A2), "r"(A3), "r"(B0), "r"(B1))
                MMA_U8(dhh,  ah0, ah1, ah2, ah3, bh0, bh1);
                MMA_U8(dmid, ah0, ah1, ah2, ah3, bl0, bl1);
                MMA_U8(dmid, al0, al1, al2, al3, bh0, bh1);
#undef MMA_U8
            }
        }
        __syncthreads();
    }
#undef PREFETCH

    const float INV = (float)(1.0 / (65535.0 * 65535.0));
#pragma unroll
    for (int nt = 0; nt < 3; nt++)
#pragma unroll
        for (int j = 0; j < 4; j++) {
            int col = nt * 8 + (l & 3) * 2 + (j & 1);
            int prow = pb + w * 16 + (l >> 2) + ((j >> 1) ? 8 : 0);
            if (col < NC) {
                float v = fmaf(65536.f, (float)dhh[nt][j], 256.f * (float)dmid[nt][j]);
                g_qbf[n][ksb][col][prow] = v * INV;
            }
        }
}

// heterogeneous grid: gemm (tensor pipe) first, conv (fma/lds) and qlo sums fill in.
__global__ __launch_bounds__(128) void work_kernel() {
    __shared__ WorkSm sm;
    int b = blockIdx.x;
    if (b < NGEMM)              gemm_body(sm.g, b);
    else if (b < NGEMM + NCONV) conv_body(sm.c, b - NGEMM);
    else                        qlosum_body(b - NGEMM - NCONV);
}

// combine (8 qbf slices + ll compensation + spatial) + softmax + u8 re-pack
__global__ void fuse2_kernel(float* __restrict__ dout, int last) {
    int t = blockIdx.x * 256 + threadIdx.x;
    if (t >= NB * NP) return;
    int n = t >> 12, p = t & 4095;
    const float COMPF = (float)(1.0 / (65535.0 * 65535.0 * 512.0));
    float kls[KS];
#pragma unroll
    for (int sl = 0; sl < KS; sl++) kls[sl] = g_klosum[n][sl][p];
    float logit[NC]; float m = -1e30f;
#pragma unroll
    for (int c = 0; c < NC; c++) {
        float b8 = 0.f, comp = 0.f;
#pragma unroll
        for (int sl = 0; sl < KS; sl++) {
            b8 += g_qbf[n][sl][c][p];
            comp = fmaf(kls[sl], (float)g_qlosumcur[n][sl][c], comp);
        }
        b8 = fmaf(comp, COMPF, b8);   // mean of the dropped Klo*qlo chain
        float s = g_comb[n][c][p];
        float lg = g_U[n][c][p] + fmaf(4.0f, b8, 2.0f * s); // COMPAT_BF, COMPAT_SPATIAL
        logit[c] = lg; m = fmaxf(m, lg);
    }
    float sum = 0.f;
#pragma unroll
    for (int c = 0; c < NC; c++) { float e = __expf(logit[c] - m); logit[c] = e; sum += e; }
    float inv = 1.0f / sum;
#pragma unroll
    for (int c = 0; c < NC; c++) {
        float qq = logit[c] * inv;
        g_q[n][c][p] = qq;
        unsigned Qq = quant16(qq);
        g_qhi[n][c][p] = (unsigned char)(Qq >> 8);
        g_qlo[n][c][p] = (unsigned char)(Qq & 255u);
        if (last) dout[(n * NC + c) * NP + p] = qq;
    }
}

extern "C" void kernel_launch(void* const* d_in, const int* in_sizes, int n_in,
                              void* d_out, int out_size) {
    const float* unary = (const float*)d_in[0];
    const float* ref   = (const float*)d_in[1];
    const float* gk    = (const float*)d_in[2];
    const float* kstd  = (const float*)d_in[3];
    float* dout = (float*)d_out;

    prep_kernel<<<32, 256>>>(unary, ref, kstd);
    g1_kernel<<<1, 128>>>(gk);
    buildk_kernel<<<dim3(64, 64, NB), 256>>>();
    klosum_kernel<<<dim3(NP / 8, NB), 256>>>();
    for (int it = 0; it < 5; it++) {
        work_kernel<<<NGEMM + NCONV + NSUM, 128>>>();
        fuse2_kernel<<<32, 256>>>(dout, it == 4);
    }
}